// round 12
// baseline (speedup 1.0000x reference)
#include <cuda_runtime.h>
#include <cuda_bf16.h>

#define NN   100000
#define NE   1600000
#define KDIM 128
#define NCLS 40

// ---------------- scratch (device globals; device-code access ONLY) ----------
// NOTE: never pass these as host-side kernel arguments — host code binds the
// host shadow object (HMM migration -> mem-delta violation, rounds 2-4).
__device__ uint4 g_Zh[NN * 16];       // 25.6 MB  bf16 Z rows (128-dim layers; also
                                      //          reused as 80B bf16 rows for layer 3)
__device__ float g_A[NN * KDIM];      // 51.2 MB  agg output (next GEMM input)
__device__ int   g_counts[NN];
__device__ int   g_rowbeg[NN];
__device__ int   g_cursor[NN];
__device__ int   g_esrc[NE];
__device__ int   g_total;

// ---------------- CSR build ----------------
__global__ void k_zero() {
    int i = blockIdx.x * 256 + threadIdx.x;
    if (i < NN) g_counts[i] = 0;
    if (i == 0) g_total = 0;
}

__global__ void k_hist(const int* __restrict__ dst) {
    int i = blockIdx.x * 256 + threadIdx.x;
    if (i < NE) atomicAdd(&g_counts[dst[i]], 1);
}

// Per-node segment base via one global atomic (order arbitrary; sets exact).
__global__ void k_base() {
    int v = blockIdx.x * 256 + threadIdx.x;
    if (v < NN) {
        int c = g_counts[v];
        int b = atomicAdd(&g_total, c);
        g_rowbeg[v] = b;
        g_cursor[v] = b;
    }
}

__global__ void k_scatter(const int* __restrict__ src, const int* __restrict__ dst) {
    int i = blockIdx.x * 256 + threadIdx.x;
    if (i < NE) {
        int p = atomicAdd(&g_cursor[dst[i]], 1);
        g_esrc[p] = src[i];
    }
}

// ---------------- aggregation (128-dim, bf16 payload) + bias + relu ----------
// FOUR nodes per warp: 8 lanes per node. Each lane gathers 2 uint4 (32 B) per
// edge; 8 lanes cover the 256 B row. 4 independent edge streams x 2-deep
// unroll x 2 loads = 16 gathers in flight per warp.
__device__ __forceinline__ void bf16x8_acc(float4& a, float4& b, uint4 v) {
    __nv_bfloat162 p0 = *reinterpret_cast<__nv_bfloat162*>(&v.x);
    __nv_bfloat162 p1 = *reinterpret_cast<__nv_bfloat162*>(&v.y);
    __nv_bfloat162 p2 = *reinterpret_cast<__nv_bfloat162*>(&v.z);
    __nv_bfloat162 p3 = *reinterpret_cast<__nv_bfloat162*>(&v.w);
    float2 f0 = __bfloat1622float2(p0);
    float2 f1 = __bfloat1622float2(p1);
    float2 f2 = __bfloat1622float2(p2);
    float2 f3 = __bfloat1622float2(p3);
    a.x += f0.x; a.y += f0.y; a.z += f1.x; a.w += f1.y;
    b.x += f2.x; b.y += f2.y; b.z += f3.x; b.w += f3.y;
}

__global__ void k_agg_relu128(const float* __restrict__ bias) {
    int warp = (blockIdx.x * blockDim.x + threadIdx.x) >> 5;
    int group = (threadIdx.x >> 3) & 3;   // 4 nodes per warp
    int node = warp * 4 + group;
    if (node >= NN) return;
    int gl = threadIdx.x & 7;             // lane within group
    const uint4* __restrict__ x = g_Zh;   // row = 16 uint4
    int beg = g_rowbeg[node];
    int end = beg + g_counts[node];

    float4 c0 = make_float4(0.f, 0.f, 0.f, 0.f);
    float4 c1 = c0, c2 = c0, c3 = c0;

    int e = beg;
    for (; e + 2 <= end; e += 2) {
        int s0 = __ldg(&g_esrc[e + 0]);
        int s1 = __ldg(&g_esrc[e + 1]);
        uint4 v00 = __ldg(&x[(size_t)s0 * 16 + gl * 2 + 0]);
        uint4 v01 = __ldg(&x[(size_t)s0 * 16 + gl * 2 + 1]);
        uint4 v10 = __ldg(&x[(size_t)s1 * 16 + gl * 2 + 0]);
        uint4 v11 = __ldg(&x[(size_t)s1 * 16 + gl * 2 + 1]);
        bf16x8_acc(c0, c1, v00);
        bf16x8_acc(c2, c3, v01);
        bf16x8_acc(c0, c1, v10);
        bf16x8_acc(c2, c3, v11);
    }
    if (e < end) {
        int s = __ldg(&g_esrc[e]);
        uint4 v0 = __ldg(&x[(size_t)s * 16 + gl * 2 + 0]);
        uint4 v1 = __ldg(&x[(size_t)s * 16 + gl * 2 + 1]);
        bf16x8_acc(c0, c1, v0);
        bf16x8_acc(c2, c3, v1);
    }
    // lane gl covers float4 slots gl*4 .. gl*4+3 of the 32-float4 output row
    const float4* b4 = (const float4*)bias;
    float4 b0 = __ldg(&b4[gl * 4 + 0]);
    float4 b1 = __ldg(&b4[gl * 4 + 1]);
    float4 b2 = __ldg(&b4[gl * 4 + 2]);
    float4 b3 = __ldg(&b4[gl * 4 + 3]);
    float4 r0, r1, r2, r3;
    r0.x = fmaxf(c0.x + b0.x, 0.f); r0.y = fmaxf(c0.y + b0.y, 0.f);
    r0.z = fmaxf(c0.z + b0.z, 0.f); r0.w = fmaxf(c0.w + b0.w, 0.f);
    r1.x = fmaxf(c1.x + b1.x, 0.f); r1.y = fmaxf(c1.y + b1.y, 0.f);
    r1.z = fmaxf(c1.z + b1.z, 0.f); r1.w = fmaxf(c1.w + b1.w, 0.f);
    r2.x = fmaxf(c2.x + b2.x, 0.f); r2.y = fmaxf(c2.y + b2.y, 0.f);
    r2.z = fmaxf(c2.z + b2.z, 0.f); r2.w = fmaxf(c2.w + b2.w, 0.f);
    r3.x = fmaxf(c3.x + b3.x, 0.f); r3.y = fmaxf(c3.y + b3.y, 0.f);
    r3.z = fmaxf(c3.z + b3.z, 0.f); r3.w = fmaxf(c3.w + b3.w, 0.f);
    float4* outp = (float4*)g_A;
    size_t ob = (size_t)node * 32 + gl * 4;
    outp[ob + 0] = r0;
    outp[ob + 1] = r1;
    outp[ob + 2] = r2;
    outp[ob + 3] = r3;
}

// ---------------- aggregation (40-dim, bf16 payload) + bias + relu -----------
// One node per warp; lanes 0-9 each gather one uint2 (4 bf16) per edge
// (10 lanes cover the 80 B row). fp32 accumulate; float4 output to d_out.
__global__ void k_agg_relu40(const float* __restrict__ bias,
                             float* __restrict__ outp) {
    int gw = (blockIdx.x * blockDim.x + threadIdx.x) >> 5;
    if (gw >= NN) return;
    const uint2* __restrict__ z = (const uint2*)g_Zh;  // row = 10 uint2 (80 B)
    int lane = threadIdx.x & 31;
    bool act = lane < 10;
    int beg = g_rowbeg[gw];
    int end = beg + g_counts[gw];

    float4 a0 = make_float4(0.f, 0.f, 0.f, 0.f);
    float4 a1 = a0, a2 = a0, a3 = a0;

    int e = beg;
    for (; e + 4 <= end; e += 4) {
        int s0 = __ldg(&g_esrc[e + 0]);
        int s1 = __ldg(&g_esrc[e + 1]);
        int s2 = __ldg(&g_esrc[e + 2]);
        int s3 = __ldg(&g_esrc[e + 3]);
        if (act) {
            uint2 v0 = __ldg(&z[(size_t)s0 * 10 + lane]);
            uint2 v1 = __ldg(&z[(size_t)s1 * 10 + lane]);
            uint2 v2 = __ldg(&z[(size_t)s2 * 10 + lane]);
            uint2 v3 = __ldg(&z[(size_t)s3 * 10 + lane]);
            __nv_bfloat162 q;
            float2 f;
            q = *reinterpret_cast<__nv_bfloat162*>(&v0.x); f = __bfloat1622float2(q); a0.x += f.x; a0.y += f.y;
            q = *reinterpret_cast<__nv_bfloat162*>(&v0.y); f = __bfloat1622float2(q); a0.z += f.x; a0.w += f.y;
            q = *reinterpret_cast<__nv_bfloat162*>(&v1.x); f = __bfloat1622float2(q); a1.x += f.x; a1.y += f.y;
            q = *reinterpret_cast<__nv_bfloat162*>(&v1.y); f = __bfloat1622float2(q); a1.z += f.x; a1.w += f.y;
            q = *reinterpret_cast<__nv_bfloat162*>(&v2.x); f = __bfloat1622float2(q); a2.x += f.x; a2.y += f.y;
            q = *reinterpret_cast<__nv_bfloat162*>(&v2.y); f = __bfloat1622float2(q); a2.z += f.x; a2.w += f.y;
            q = *reinterpret_cast<__nv_bfloat162*>(&v3.x); f = __bfloat1622float2(q); a3.x += f.x; a3.y += f.y;
            q = *reinterpret_cast<__nv_bfloat162*>(&v3.y); f = __bfloat1622float2(q); a3.z += f.x; a3.w += f.y;
        }
    }
    for (; e < end; e++) {
        int s = __ldg(&g_esrc[e]);
        if (act) {
            uint2 v = __ldg(&z[(size_t)s * 10 + lane]);
            __nv_bfloat162 q;
            float2 f;
            q = *reinterpret_cast<__nv_bfloat162*>(&v.x); f = __bfloat1622float2(q); a0.x += f.x; a0.y += f.y;
            q = *reinterpret_cast<__nv_bfloat162*>(&v.y); f = __bfloat1622float2(q); a0.z += f.x; a0.w += f.y;
        }
    }
    if (act) {
        float4 b = __ldg(&((const float4*)bias)[lane]);
        float4 r;
        r.x = fmaxf(((a0.x + a1.x) + (a2.x + a3.x)) + b.x, 0.f);
        r.y = fmaxf(((a0.y + a1.y) + (a2.y + a3.y)) + b.y, 0.f);
        r.z = fmaxf(((a0.z + a1.z) + (a2.z + a3.z)) + b.z, 0.f);
        r.w = fmaxf(((a0.w + a1.w) + (a2.w + a3.w)) + b.w, 0.f);
        ((float4*)outp)[(size_t)gw * 10 + lane] = r;
    }
}

// ---------------- GEMM 128-col -> bf16 Z: Zh[M,128] = A[M,128] @ W[128,128] --
// BM=128, BN=128, BK=16, 256 threads, 8x8 per thread. Epilogue packs bf16.
__global__ void __launch_bounds__(256) k_gemm128(const float* __restrict__ Aext,
                                                 const float* __restrict__ W) {
    __shared__ float As[16][132];
    __shared__ float Bs[16][132];
    const float* __restrict__ A = Aext ? Aext : g_A;

    int t = threadIdx.x;
    int tx = t & 15, ty = t >> 4;
    int m0 = blockIdx.x * 128;

    float acc[8][8];
#pragma unroll
    for (int i = 0; i < 8; i++)
#pragma unroll
        for (int j = 0; j < 8; j++) acc[i][j] = 0.f;

    for (int kc = 0; kc < 8; kc++) {
#pragma unroll
        for (int i = 0; i < 2; i++) {
            int f = t + i * 256;
            int row = f >> 2, kq = f & 3;
            float4 v = make_float4(0.f, 0.f, 0.f, 0.f);
            if (m0 + row < NN)
                v = *(const float4*)(A + (size_t)(m0 + row) * KDIM + kc * 16 + kq * 4);
            As[kq * 4 + 0][row] = v.x;
            As[kq * 4 + 1][row] = v.y;
            As[kq * 4 + 2][row] = v.z;
            As[kq * 4 + 3][row] = v.w;
        }
#pragma unroll
        for (int i = 0; i < 2; i++) {
            int r = (t >> 5) + i * 8;
            int c = (t & 31) * 4;
            *(float4*)&Bs[r][c] = *(const float4*)(W + (size_t)(kc * 16 + r) * KDIM + c);
        }
        __syncthreads();
#pragma unroll
        for (int kk = 0; kk < 16; kk++) {
            float4 aA = *(const float4*)&As[kk][ty * 8];
            float4 aB = *(const float4*)&As[kk][ty * 8 + 4];
            float4 bA = *(const float4*)&Bs[kk][tx * 8];
            float4 bB = *(const float4*)&Bs[kk][tx * 8 + 4];
            float a[8] = {aA.x, aA.y, aA.z, aA.w, aB.x, aB.y, aB.z, aB.w};
            float b[8] = {bA.x, bA.y, bA.z, bA.w, bB.x, bB.y, bB.z, bB.w};
#pragma unroll
            for (int i = 0; i < 8; i++)
#pragma unroll
                for (int j = 0; j < 8; j++) acc[i][j] = fmaf(a[i], b[j], acc[i][j]);
        }
        __syncthreads();
    }
    // epilogue: pack 8 fp32 -> 8 bf16 (16 B = one uint4) per row
#pragma unroll
    for (int i = 0; i < 8; i++) {
        int row = m0 + ty * 8 + i;
        if (row < NN) {
            __nv_bfloat162 p0 = __floats2bfloat162_rn(acc[i][0], acc[i][1]);
            __nv_bfloat162 p1 = __floats2bfloat162_rn(acc[i][2], acc[i][3]);
            __nv_bfloat162 p2 = __floats2bfloat162_rn(acc[i][4], acc[i][5]);
            __nv_bfloat162 p3 = __floats2bfloat162_rn(acc[i][6], acc[i][7]);
            uint4 w;
            w.x = *reinterpret_cast<unsigned*>(&p0);
            w.y = *reinterpret_cast<unsigned*>(&p1);
            w.z = *reinterpret_cast<unsigned*>(&p2);
            w.w = *reinterpret_cast<unsigned*>(&p3);
            g_Zh[(size_t)row * 16 + tx] = w;
        }
    }
}

// ---------------- GEMM 40-col -> bf16: g_A @ W3 -> g_Zh (80 B rows) ----------
__global__ void __launch_bounds__(256) k_gemm40(const float* __restrict__ W) {
    __shared__ float As[16][132];
    __shared__ float Bs[16][68];
    const float* __restrict__ A = g_A;
    uint2* __restrict__ C = (uint2*)g_Zh;   // row = 10 uint2 (40 bf16)
    const int N = NCLS;

    int t = threadIdx.x;
    int tx = t & 15, ty = t >> 4;
    int m0 = blockIdx.x * 128;

    float acc[8][4];
#pragma unroll
    for (int i = 0; i < 8; i++)
#pragma unroll
        for (int j = 0; j < 4; j++) acc[i][j] = 0.f;

    for (int kc = 0; kc < 8; kc++) {
#pragma unroll
        for (int i = 0; i < 2; i++) {
            int f = t + i * 256;
            int row = f >> 2, kq = f & 3;
            float4 v = make_float4(0.f, 0.f, 0.f, 0.f);
            if (m0 + row < NN)
                v = *(const float4*)(A + (size_t)(m0 + row) * KDIM + kc * 16 + kq * 4);
            As[kq * 4 + 0][row] = v.x;
            As[kq * 4 + 1][row] = v.y;
            As[kq * 4 + 2][row] = v.z;
            As[kq * 4 + 3][row] = v.w;
        }
        {
            int r = t >> 4, cq = t & 15;
#pragma unroll
            for (int j = 0; j < 4; j++) {
                int col = cq * 4 + j;
                Bs[r][cq * 4 + j] = (col < N) ? W[(size_t)(kc * 16 + r) * N + col] : 0.f;
            }
        }
        __syncthreads();
#pragma unroll
        for (int kk = 0; kk < 16; kk++) {
            float4 aA = *(const float4*)&As[kk][ty * 8];
            float4 aB = *(const float4*)&As[kk][ty * 8 + 4];
            float4 bv = *(const float4*)&Bs[kk][tx * 4];
            float a[8] = {aA.x, aA.y, aA.z, aA.w, aB.x, aB.y, aB.z, aB.w};
            float b[4] = {bv.x, bv.y, bv.z, bv.w};
#pragma unroll
            for (int i = 0; i < 8; i++)
#pragma unroll
                for (int j = 0; j < 4; j++) acc[i][j] = fmaf(a[i], b[j], acc[i][j]);
        }
        __syncthreads();
    }
    // epilogue: cols tx*4..tx*4+3 -> one uint2 (4 bf16) when tx < 10
    if (tx < 10) {
#pragma unroll
        for (int i = 0; i < 8; i++) {
            int row = m0 + ty * 8 + i;
            if (row < NN) {
                __nv_bfloat162 p0 = __floats2bfloat162_rn(acc[i][0], acc[i][1]);
                __nv_bfloat162 p1 = __floats2bfloat162_rn(acc[i][2], acc[i][3]);
                uint2 w;
                w.x = *reinterpret_cast<unsigned*>(&p0);
                w.y = *reinterpret_cast<unsigned*>(&p1);
                C[(size_t)row * 10 + tx] = w;
            }
        }
    }
}

// ---------------- launch ----------------
extern "C" void kernel_launch(void* const* d_in, const int* in_sizes, int n_in,
                              void* d_out, int out_size) {
    const float* feats = (const float*)d_in[0];
    const int*   src   = (const int*)d_in[1];
    const int*   dst   = (const int*)d_in[2];
    const float* W1 = (const float*)d_in[3];
    const float* b1 = (const float*)d_in[4];
    const float* W2 = (const float*)d_in[5];
    const float* b2 = (const float*)d_in[6];
    const float* W3 = (const float*)d_in[7];
    const float* b3 = (const float*)d_in[8];
    float* out = (float*)d_out;

    // One-time resource init (first call is the non-captured correctness run).
    static cudaStream_t s1 = nullptr;
    static cudaEvent_t  eFork = nullptr, eJoin = nullptr;
    if (!s1) {
        cudaStreamCreateWithFlags(&s1, cudaStreamNonBlocking);
        cudaEventCreateWithFlags(&eFork, cudaEventDisableTiming);
        cudaEventCreateWithFlags(&eJoin, cudaEventDisableTiming);
    }

    const int AGG128_BLOCKS = ((NN + 3) / 4 * 32 + 255) / 256;  // 4 nodes/warp
    const int AGG40_BLOCKS  = (NN * 32 + 255) / 256;            // 1 node/warp
    const int GB = (NN + 127) / 128;                            // 782

    // Fork: CSR build on s1, concurrent with GEMM1 on the main stream.
    cudaEventRecord(eFork, 0);
    cudaStreamWaitEvent(s1, eFork, 0);
    k_zero<<<(NN + 255) / 256, 256, 0, s1>>>();
    k_hist<<<(NE + 255) / 256, 256, 0, s1>>>(dst);
    k_base<<<(NN + 255) / 256, 256, 0, s1>>>();
    k_scatter<<<(NE + 255) / 256, 256, 0, s1>>>(src, dst);
    cudaEventRecord(eJoin, s1);

    // Main stream: Layer-1 GEMM needs only feats/W1 (independent of CSR).
    k_gemm128<<<GB, 256>>>(feats, W1);               // feats -> g_Zh (bf16)

    // Join: aggregation needs the CSR.
    cudaStreamWaitEvent(0, eJoin, 0);
    k_agg_relu128<<<AGG128_BLOCKS, 256>>>(b1);       // g_Zh -> g_A (fp32)
    // Layer 2
    k_gemm128<<<GB, 256>>>(nullptr, W2);             // g_A -> g_Zh (bf16)
    k_agg_relu128<<<AGG128_BLOCKS, 256>>>(b2);       // g_Zh -> g_A (fp32)
    // Layer 3: bf16 projection, bf16 gather
    k_gemm40<<<GB, 256>>>(W3);                       // g_A -> g_Zh (80B bf16 rows)
    k_agg_relu40<<<AGG40_BLOCKS, 256>>>(b3, out);    // g_Zh -> d_out
}

// round 16
// speedup vs baseline: 1.2310x; 1.2310x over previous
#include <cuda_runtime.h>
#include <cuda_bf16.h>
#include <cstdint>

#define NN   100000
#define NE   1600000
#define KDIM 128
#define NCLS 40

// ---------------- scratch (device globals; device-code access ONLY) ----------
// NOTE: never pass these as host-side kernel arguments — host code binds the
// host shadow object (HMM migration -> mem-delta violation, rounds 2-4).
__device__ uint4 g_Zh[NN * 16];       // 25.6 MB  bf16 Z rows (128-dim layers; also
                                      //          reused as 80B bf16 rows for layer 3)
__device__ float g_A[NN * KDIM];      // 51.2 MB  agg output (next GEMM input)
__device__ int   g_counts[NN];
__device__ int   g_rowbeg[NN];
__device__ int   g_cursor[NN];
__device__ int   g_esrc[NE];
__device__ int   g_total;

// ---------------- CSR build ----------------
__global__ void k_zero() {
    int i = blockIdx.x * 256 + threadIdx.x;
    if (i < NN) g_counts[i] = 0;
    if (i == 0) g_total = 0;
}

__global__ void k_hist(const int* __restrict__ dst) {
    int i = blockIdx.x * 256 + threadIdx.x;
    if (i < NE) atomicAdd(&g_counts[dst[i]], 1);
}

// Per-node segment base via one global atomic (order arbitrary; sets exact).
__global__ void k_base() {
    int v = blockIdx.x * 256 + threadIdx.x;
    if (v < NN) {
        int c = g_counts[v];
        int b = atomicAdd(&g_total, c);
        g_rowbeg[v] = b;
        g_cursor[v] = b;
    }
}

__global__ void k_scatter(const int* __restrict__ src, const int* __restrict__ dst) {
    int i = blockIdx.x * 256 + threadIdx.x;
    if (i < NE) {
        int p = atomicAdd(&g_cursor[dst[i]], 1);
        g_esrc[p] = src[i];
    }
}

// ---------------- aggregation (128-dim, bf16 payload) + bias + relu ----------
// TWO nodes per warp (round-11 proven): lanes 0-15 -> node 2w, 16-31 -> 2w+1.
// Each lane gathers one uint4 (8 bf16) per edge; 16 lanes cover the 256B row.
__device__ __forceinline__ void bf16x8_add(float4& a, float4& b, uint4 v) {
    __nv_bfloat162 p0 = *reinterpret_cast<__nv_bfloat162*>(&v.x);
    __nv_bfloat162 p1 = *reinterpret_cast<__nv_bfloat162*>(&v.y);
    __nv_bfloat162 p2 = *reinterpret_cast<__nv_bfloat162*>(&v.z);
    __nv_bfloat162 p3 = *reinterpret_cast<__nv_bfloat162*>(&v.w);
    float2 f0 = __bfloat1622float2(p0);
    float2 f1 = __bfloat1622float2(p1);
    float2 f2 = __bfloat1622float2(p2);
    float2 f3 = __bfloat1622float2(p3);
    a.x += f0.x; a.y += f0.y; a.z += f1.x; a.w += f1.y;
    b.x += f2.x; b.y += f2.y; b.z += f3.x; b.w += f3.y;
}

__global__ void k_agg_relu128(const float* __restrict__ bias) {
    int warp = (blockIdx.x * blockDim.x + threadIdx.x) >> 5;
    int half = (threadIdx.x >> 4) & 1;
    int node = warp * 2 + half;
    if (node >= NN) return;
    int hl = threadIdx.x & 15;          // lane within half-warp
    const uint4* __restrict__ x = g_Zh; // row = 16 uint4
    int beg = g_rowbeg[node];
    int end = beg + g_counts[node];

    float4 aA0 = make_float4(0.f, 0.f, 0.f, 0.f);
    float4 aB0 = aA0, aA1 = aA0, aB1 = aA0;

    int e = beg;
    for (; e + 4 <= end; e += 4) {
        int s0 = __ldg(&g_esrc[e + 0]);
        int s1 = __ldg(&g_esrc[e + 1]);
        int s2 = __ldg(&g_esrc[e + 2]);
        int s3 = __ldg(&g_esrc[e + 3]);
        uint4 v0 = __ldg(&x[(size_t)s0 * 16 + hl]);
        uint4 v1 = __ldg(&x[(size_t)s1 * 16 + hl]);
        uint4 v2 = __ldg(&x[(size_t)s2 * 16 + hl]);
        uint4 v3 = __ldg(&x[(size_t)s3 * 16 + hl]);
        bf16x8_add(aA0, aB0, v0);
        bf16x8_add(aA1, aB1, v1);
        bf16x8_add(aA0, aB0, v2);
        bf16x8_add(aA1, aB1, v3);
    }
    for (; e < end; e++) {
        int s = __ldg(&g_esrc[e]);
        uint4 v = __ldg(&x[(size_t)s * 16 + hl]);
        bf16x8_add(aA0, aB0, v);
    }
    const float4* b4 = (const float4*)bias;
    float4 bA = __ldg(&b4[hl * 2]);
    float4 bB = __ldg(&b4[hl * 2 + 1]);
    float4 rA, rB;
    rA.x = fmaxf((aA0.x + aA1.x) + bA.x, 0.f);
    rA.y = fmaxf((aA0.y + aA1.y) + bA.y, 0.f);
    rA.z = fmaxf((aA0.z + aA1.z) + bA.z, 0.f);
    rA.w = fmaxf((aA0.w + aA1.w) + bA.w, 0.f);
    rB.x = fmaxf((aB0.x + aB1.x) + bB.x, 0.f);
    rB.y = fmaxf((aB0.y + aB1.y) + bB.y, 0.f);
    rB.z = fmaxf((aB0.z + aB1.z) + bB.z, 0.f);
    rB.w = fmaxf((aB0.w + aB1.w) + bB.w, 0.f);
    float4* outp = (float4*)g_A;
    outp[(size_t)node * 32 + hl * 2]     = rA;
    outp[(size_t)node * 32 + hl * 2 + 1] = rB;
}

// ---------------- aggregation (40-dim, bf16 payload) + bias + relu -----------
// One node per warp; lanes 0-9 each gather one uint2 (4 bf16) per edge
// (10 lanes cover the 80 B row). fp32 accumulate; float4 output to d_out.
__global__ void k_agg_relu40(const float* __restrict__ bias,
                             float* __restrict__ outp) {
    int gw = (blockIdx.x * blockDim.x + threadIdx.x) >> 5;
    if (gw >= NN) return;
    const uint2* __restrict__ z = (const uint2*)g_Zh;  // row = 10 uint2 (80 B)
    int lane = threadIdx.x & 31;
    bool act = lane < 10;
    int beg = g_rowbeg[gw];
    int end = beg + g_counts[gw];

    float4 a0 = make_float4(0.f, 0.f, 0.f, 0.f);
    float4 a1 = a0, a2 = a0, a3 = a0;

    int e = beg;
    for (; e + 4 <= end; e += 4) {
        int s0 = __ldg(&g_esrc[e + 0]);
        int s1 = __ldg(&g_esrc[e + 1]);
        int s2 = __ldg(&g_esrc[e + 2]);
        int s3 = __ldg(&g_esrc[e + 3]);
        if (act) {
            uint2 v0 = __ldg(&z[(size_t)s0 * 10 + lane]);
            uint2 v1 = __ldg(&z[(size_t)s1 * 10 + lane]);
            uint2 v2 = __ldg(&z[(size_t)s2 * 10 + lane]);
            uint2 v3 = __ldg(&z[(size_t)s3 * 10 + lane]);
            __nv_bfloat162 q;
            float2 f;
            q = *reinterpret_cast<__nv_bfloat162*>(&v0.x); f = __bfloat1622float2(q); a0.x += f.x; a0.y += f.y;
            q = *reinterpret_cast<__nv_bfloat162*>(&v0.y); f = __bfloat1622float2(q); a0.z += f.x; a0.w += f.y;
            q = *reinterpret_cast<__nv_bfloat162*>(&v1.x); f = __bfloat1622float2(q); a1.x += f.x; a1.y += f.y;
            q = *reinterpret_cast<__nv_bfloat162*>(&v1.y); f = __bfloat1622float2(q); a1.z += f.x; a1.w += f.y;
            q = *reinterpret_cast<__nv_bfloat162*>(&v2.x); f = __bfloat1622float2(q); a2.x += f.x; a2.y += f.y;
            q = *reinterpret_cast<__nv_bfloat162*>(&v2.y); f = __bfloat1622float2(q); a2.z += f.x; a2.w += f.y;
            q = *reinterpret_cast<__nv_bfloat162*>(&v3.x); f = __bfloat1622float2(q); a3.x += f.x; a3.y += f.y;
            q = *reinterpret_cast<__nv_bfloat162*>(&v3.y); f = __bfloat1622float2(q); a3.z += f.x; a3.w += f.y;
        }
    }
    for (; e < end; e++) {
        int s = __ldg(&g_esrc[e]);
        if (act) {
            uint2 v = __ldg(&z[(size_t)s * 10 + lane]);
            __nv_bfloat162 q;
            float2 f;
            q = *reinterpret_cast<__nv_bfloat162*>(&v.x); f = __bfloat1622float2(q); a0.x += f.x; a0.y += f.y;
            q = *reinterpret_cast<__nv_bfloat162*>(&v.y); f = __bfloat1622float2(q); a0.z += f.x; a0.w += f.y;
        }
    }
    if (act) {
        float4 b = __ldg(&((const float4*)bias)[lane]);
        float4 r;
        r.x = fmaxf(((a0.x + a1.x) + (a2.x + a3.x)) + b.x, 0.f);
        r.y = fmaxf(((a0.y + a1.y) + (a2.y + a3.y)) + b.y, 0.f);
        r.z = fmaxf(((a0.z + a1.z) + (a2.z + a3.z)) + b.z, 0.f);
        r.w = fmaxf(((a0.w + a1.w) + (a2.w + a3.w)) + b.w, 0.f);
        ((float4*)outp)[(size_t)gw * 10 + lane] = r;
    }
}

// ---------------- tf32 helper ----------------
__device__ __forceinline__ float tf32_rna(float x) {
    unsigned int u;
    asm("cvt.rna.tf32.f32 %0, %1;" : "=r"(u) : "f"(x));
    return __uint_as_float(u);
}

// ---------------- GEMM 128-col (tf32 MMA) -> bf16 Z --------------------------
// Zh[M,128] = A[M,128] @ W[128,128]. BM=128, BN=128, 256 threads = 8 warps
// in a 4(M)x2(N) grid; each warp computes 32x64 via 2x8 m16n8k8 tf32 tiles.
// SMEM staged tf32-rounded; row stride 136 floats -> conflict-free frag LDS.
__global__ void __launch_bounds__(256) k_gemm128(const float* __restrict__ Aext,
                                                 const float* __restrict__ W) {
    __shared__ float As[16][136];   // [k][m], tf32-rounded
    __shared__ float Bs[16][136];   // [k][n], tf32-rounded
    const float* __restrict__ A = Aext ? Aext : g_A;

    int t = threadIdx.x;
    int wid = t >> 5, lane = t & 31;
    int gid = lane >> 2, tig = lane & 3;
    int warpM = (wid >> 1) * 32;
    int warpN = (wid & 1) * 64;
    int m0 = blockIdx.x * 128;

    float c[2][8][4];
#pragma unroll
    for (int mt = 0; mt < 2; mt++)
#pragma unroll
        for (int nt = 0; nt < 8; nt++)
#pragma unroll
            for (int j = 0; j < 4; j++) c[mt][nt][j] = 0.f;

    for (int kc = 0; kc < 8; kc++) {
        // stage A tile 128x16 -> transposed As[k][m]
#pragma unroll
        for (int i = 0; i < 2; i++) {
            int f = t + i * 256;
            int row = f >> 2, kq = f & 3;
            float4 v = make_float4(0.f, 0.f, 0.f, 0.f);
            if (m0 + row < NN)
                v = *(const float4*)(A + (size_t)(m0 + row) * KDIM + kc * 16 + kq * 4);
            As[kq * 4 + 0][row] = tf32_rna(v.x);
            As[kq * 4 + 1][row] = tf32_rna(v.y);
            As[kq * 4 + 2][row] = tf32_rna(v.z);
            As[kq * 4 + 3][row] = tf32_rna(v.w);
        }
        // stage B tile 16x128 natural layout
#pragma unroll
        for (int i = 0; i < 2; i++) {
            int r = (t >> 5) + i * 8;
            int cb = (t & 31) * 4;
            float4 v = *(const float4*)(W + (size_t)(kc * 16 + r) * KDIM + cb);
            Bs[r][cb + 0] = tf32_rna(v.x);
            Bs[r][cb + 1] = tf32_rna(v.y);
            Bs[r][cb + 2] = tf32_rna(v.z);
            Bs[r][cb + 3] = tf32_rna(v.w);
        }
        __syncthreads();
#pragma unroll
        for (int ks = 0; ks < 2; ks++) {
            int kb = ks * 8;
            unsigned int a[2][4];
#pragma unroll
            for (int mt = 0; mt < 2; mt++) {
                int mr = warpM + mt * 16 + gid;
                a[mt][0] = __float_as_uint(As[kb + tig    ][mr]);
                a[mt][1] = __float_as_uint(As[kb + tig    ][mr + 8]);
                a[mt][2] = __float_as_uint(As[kb + tig + 4][mr]);
                a[mt][3] = __float_as_uint(As[kb + tig + 4][mr + 8]);
            }
            unsigned int b[8][2];
#pragma unroll
            for (int nt = 0; nt < 8; nt++) {
                int nc = warpN + nt * 8 + gid;
                b[nt][0] = __float_as_uint(Bs[kb + tig    ][nc]);
                b[nt][1] = __float_as_uint(Bs[kb + tig + 4][nc]);
            }
#pragma unroll
            for (int mt = 0; mt < 2; mt++)
#pragma unroll
                for (int nt = 0; nt < 8; nt++)
                    asm volatile(
                        "mma.sync.aligned.m16n8k8.row.col.f32.tf32.tf32.f32 "
                        "{%0,%1,%2,%3}, {%4,%5,%6,%7}, {%8,%9}, {%0,%1,%2,%3};"
                        : "+f"(c[mt][nt][0]), "+f"(c[mt][nt][1]),
                          "+f"(c[mt][nt][2]), "+f"(c[mt][nt][3])
                        : "r"(a[mt][0]), "r"(a[mt][1]), "r"(a[mt][2]), "r"(a[mt][3]),
                          "r"(b[nt][0]), "r"(b[nt][1]));
        }
        __syncthreads();
    }
    // epilogue: c0/c1 = row gid cols 2tig/2tig+1; c2/c3 = row gid+8.
    // Pack each fp32 pair -> bf16x2 (one 4B store into the 64-uint32 row).
    unsigned int* Z = (unsigned int*)g_Zh;
#pragma unroll
    for (int mt = 0; mt < 2; mt++) {
        int r0 = m0 + warpM + mt * 16 + gid;
        int r1 = r0 + 8;
#pragma unroll
        for (int nt = 0; nt < 8; nt++) {
            int cw = (warpN + nt * 8) / 2 + tig;   // uint32 (bf16-pair) column
            if (r0 < NN) {
                __nv_bfloat162 p = __floats2bfloat162_rn(c[mt][nt][0], c[mt][nt][1]);
                Z[(size_t)r0 * 64 + cw] = *reinterpret_cast<unsigned int*>(&p);
            }
            if (r1 < NN) {
                __nv_bfloat162 p = __floats2bfloat162_rn(c[mt][nt][2], c[mt][nt][3]);
                Z[(size_t)r1 * 64 + cw] = *reinterpret_cast<unsigned int*>(&p);
            }
        }
    }
}

// ---------------- GEMM 40-col -> bf16: g_A @ W3 -> g_Zh (80 B rows) ----------
__global__ void __launch_bounds__(256) k_gemm40(const float* __restrict__ W) {
    __shared__ float As[16][132];
    __shared__ float Bs[16][68];
    const float* __restrict__ A = g_A;
    uint2* __restrict__ C = (uint2*)g_Zh;   // row = 10 uint2 (40 bf16)
    const int N = NCLS;

    int t = threadIdx.x;
    int tx = t & 15, ty = t >> 4;
    int m0 = blockIdx.x * 128;

    float acc[8][4];
#pragma unroll
    for (int i = 0; i < 8; i++)
#pragma unroll
        for (int j = 0; j < 4; j++) acc[i][j] = 0.f;

    for (int kc = 0; kc < 8; kc++) {
#pragma unroll
        for (int i = 0; i < 2; i++) {
            int f = t + i * 256;
            int row = f >> 2, kq = f & 3;
            float4 v = make_float4(0.f, 0.f, 0.f, 0.f);
            if (m0 + row < NN)
                v = *(const float4*)(A + (size_t)(m0 + row) * KDIM + kc * 16 + kq * 4);
            As[kq * 4 + 0][row] = v.x;
            As[kq * 4 + 1][row] = v.y;
            As[kq * 4 + 2][row] = v.z;
            As[kq * 4 + 3][row] = v.w;
        }
        {
            int r = t >> 4, cq = t & 15;
#pragma unroll
            for (int j = 0; j < 4; j++) {
                int col = cq * 4 + j;
                Bs[r][cq * 4 + j] = (col < N) ? W[(size_t)(kc * 16 + r) * N + col] : 0.f;
            }
        }
        __syncthreads();
#pragma unroll
        for (int kk = 0; kk < 16; kk++) {
            float4 aA = *(const float4*)&As[kk][ty * 8];
            float4 aB = *(const float4*)&As[kk][ty * 8 + 4];
            float4 bv = *(const float4*)&Bs[kk][tx * 4];
            float a[8] = {aA.x, aA.y, aA.z, aA.w, aB.x, aB.y, aB.z, aB.w};
            float b[4] = {bv.x, bv.y, bv.z, bv.w};
#pragma unroll
            for (int i = 0; i < 8; i++)
#pragma unroll
                for (int j = 0; j < 4; j++) acc[i][j] = fmaf(a[i], b[j], acc[i][j]);
        }
        __syncthreads();
    }
    // epilogue: cols tx*4..tx*4+3 -> one uint2 (4 bf16) when tx < 10
    if (tx < 10) {
#pragma unroll
        for (int i = 0; i < 8; i++) {
            int row = m0 + ty * 8 + i;
            if (row < NN) {
                __nv_bfloat162 p0 = __floats2bfloat162_rn(acc[i][0], acc[i][1]);
                __nv_bfloat162 p1 = __floats2bfloat162_rn(acc[i][2], acc[i][3]);
                uint2 w;
                w.x = *reinterpret_cast<unsigned int*>(&p0);
                w.y = *reinterpret_cast<unsigned int*>(&p1);
                C[(size_t)row * 10 + tx] = w;
            }
        }
    }
}

// ---------------- launch ----------------
extern "C" void kernel_launch(void* const* d_in, const int* in_sizes, int n_in,
                              void* d_out, int out_size) {
    const float* feats = (const float*)d_in[0];
    const int*   src   = (const int*)d_in[1];
    const int*   dst   = (const int*)d_in[2];
    const float* W1 = (const float*)d_in[3];
    const float* b1 = (const float*)d_in[4];
    const float* W2 = (const float*)d_in[5];
    const float* b2 = (const float*)d_in[6];
    const float* W3 = (const float*)d_in[7];
    const float* b3 = (const float*)d_in[8];
    float* out = (float*)d_out;

    // One-time resource init (first call is the non-captured correctness run).
    static cudaStream_t s1 = nullptr;
    static cudaEvent_t  eFork = nullptr, eJoin = nullptr;
    if (!s1) {
        cudaStreamCreateWithFlags(&s1, cudaStreamNonBlocking);
        cudaEventCreateWithFlags(&eFork, cudaEventDisableTiming);
        cudaEventCreateWithFlags(&eJoin, cudaEventDisableTiming);
    }

    const int AGG128_BLOCKS = ((NN + 1) / 2 * 32 + 255) / 256;  // 2 nodes/warp
    const int AGG40_BLOCKS  = (NN * 32 + 255) / 256;            // 1 node/warp
    const int GB = (NN + 127) / 128;                            // 782

    // Fork: CSR build on s1, concurrent with GEMM1 on the main stream.
    cudaEventRecord(eFork, 0);
    cudaStreamWaitEvent(s1, eFork, 0);
    k_zero<<<(NN + 255) / 256, 256, 0, s1>>>();
    k_hist<<<(NE + 255) / 256, 256, 0, s1>>>(dst);
    k_base<<<(NN + 255) / 256, 256, 0, s1>>>();
    k_scatter<<<(NE + 255) / 256, 256, 0, s1>>>(src, dst);
    cudaEventRecord(eJoin, s1);

    // Main stream: Layer-1 GEMM needs only feats/W1 (independent of CSR).
    k_gemm128<<<GB, 256>>>(feats, W1);               // feats -> g_Zh (bf16)

    // Join: aggregation needs the CSR.
    cudaStreamWaitEvent(0, eJoin, 0);
    k_agg_relu128<<<AGG128_BLOCKS, 256>>>(b1);       // g_Zh -> g_A (fp32)
    // Layer 2
    k_gemm128<<<GB, 256>>>(nullptr, W2);             // g_A -> g_Zh (bf16)
    k_agg_relu128<<<AGG128_BLOCKS, 256>>>(b2);       // g_Zh -> g_A (fp32)
    // Layer 3: bf16 projection, bf16 gather
    k_gemm40<<<GB, 256>>>(W3);                       // g_A -> g_Zh (80B bf16 rows)
    k_agg_relu40<<<AGG40_BLOCKS, 256>>>(b3, out);    // g_Zh -> d_out
}